// round 3
// baseline (speedup 1.0000x reference)
#include <cuda_runtime.h>

#define B_SZ    256
#define T_STEPS 50
#define IDIM    16
#define D0      512
#define DIN     528
#define HID     512
#define HTOT    1040
#define DTc     0.05f
#define NSTEPS  5
#define NCTA    128
#define NT      288

#define OFF_PRED  0
#define OFF_TRAJ  204800
#define OFF_TIMES 409600
#define OFF_LASTH 409650
#define OFF_HFIN  540722

#define SMEM_FLOATS (16896 + 16384 + 16896 + 4752 + 32 + 32 + 36 + 1024 + 32)
#define SMEM_BYTES  (SMEM_FLOATS * 4)

__device__ float g_h[B_SZ * HTOT];
__device__ float g_a1[B_SZ * HID];
__device__ float g_a2[B_SZ * HID];
__device__ unsigned g_bar_arrive;
__device__ volatile unsigned g_bar_release;

__global__ void init_kernel() {
    int idx = blockIdx.x * blockDim.x + threadIdx.x;
    if (idx == 0) { g_bar_arrive = 0; g_bar_release = 0; }
    int stride = gridDim.x * blockDim.x;
    for (int i = idx; i < B_SZ * HTOT; i += stride) g_h[i] = 0.f;
}

__device__ __forceinline__ void grid_bar(unsigned &epoch) {
    __syncthreads();
    if (threadIdx.x == 0) {
        __threadfence();
        epoch++;
        unsigned prev = atomicAdd(&g_bar_arrive, 1u);
        if (prev + 1u == epoch * (unsigned)NCTA) {
            g_bar_release = epoch;
            __threadfence();
        } else {
            while (g_bar_release < epoch) { }
            __threadfence();
        }
    }
    __syncthreads();
}

__device__ __forceinline__ float4 ldcg4(const float* p) {
    return __ldcg((const float4*)p);
}

// One 32-row x ncols-col tile of OUT = act(X @ Wslab + bias).
// mode 0: dst[row*HID + cbase+cc] = relu(v)
// mode 1: g_h[row*HTOT + D0 + cbase+cc] += DT * v
__device__ void gemm_tile(const float* __restrict__ X, int ldx, int K,
                          const float* __restrict__ sW,
                          const float* __restrict__ sBias,
                          int ncols, int rbase, int cbase,
                          float* __restrict__ smx,
                          float* __restrict__ dst, int mode, int tid)
{
    int nthr = ncols << 3;
    int cc = tid % ncols;
    int rg = tid / ncols;
    float a0 = 0.f, a1 = 0.f, a2 = 0.f, a3 = 0.f;
    int chunk = K >> 2;
    int nq = chunk >> 2;

    for (int kc = 0; kc < 4; kc++) {
        int k0 = kc * chunk;
        __syncthreads();
        for (int it = tid; it < (nq << 5); it += NT) {
            int r = it / nq;
            int q = it - r * nq;
            float4 v = ldcg4(X + (rbase + r) * ldx + k0 + (q << 2));
            int kk = q << 2;
            smx[(kk + 0) * 36 + r] = v.x;
            smx[(kk + 1) * 36 + r] = v.y;
            smx[(kk + 2) * 36 + r] = v.z;
            smx[(kk + 3) * 36 + r] = v.w;
        }
        __syncthreads();
        if (tid < nthr) {
            const float* wp = sW + k0 * ncols + cc;
            const float* xp = smx + (rg << 2);
            #pragma unroll 4
            for (int kk = 0; kk < chunk; kk++) {
                float w = *wp; wp += ncols;
                float4 xv = *(const float4*)xp; xp += 36;
                a0 = fmaf(xv.x, w, a0);
                a1 = fmaf(xv.y, w, a1);
                a2 = fmaf(xv.z, w, a2);
                a3 = fmaf(xv.w, w, a3);
            }
        }
    }
    if (tid < nthr) {
        float bb = sBias[cc];
        float vals[4] = { a0 + bb, a1 + bb, a2 + bb, a3 + bb };
        #pragma unroll
        for (int j = 0; j < 4; j++) {
            int row = rbase + (rg << 2) + j;
            if (mode == 0) {
                float v = vals[j] > 0.f ? vals[j] : 0.f;
                dst[row * HID + cbase + cc] = v;
            } else {
                float* p = &g_h[row * HTOT + D0 + cbase + cc];
                float oldv = __ldcg(p);
                *p = oldv + DTc * vals[j];
            }
        }
    }
}

__global__ void __launch_bounds__(NT, 1) cnode_kernel(
    const float* __restrict__ times, const float* __restrict__ Y,
    const float* __restrict__ mask,  const float* __restrict__ A,
    const float* __restrict__ Bv,
    const float* __restrict__ W1, const float* __restrict__ b1,
    const float* __restrict__ W2, const float* __restrict__ b2,
    const float* __restrict__ W3, const float* __restrict__ b3,
    float* __restrict__ out)
{
    extern __shared__ float sm[];
    float* s_w1 = sm;                       // 528*32
    float* s_w2 = s_w1 + 528 * 32;          // 512*32
    float* s_w3 = s_w2 + 512 * 32;          // 512*33
    float* s_x  = s_w3 + 512 * 33;          // 132*36
    float* s_b1 = s_x + 132 * 36;           // 32
    float* s_b2 = s_b1 + 32;                // 32
    float* s_b3 = s_b2 + 32;                // 36
    float* s_At = s_b3 + 36;                // 1024
    float* s_Bv = s_At + 1024;              // 32
    __shared__ float s_hd[32];
    __shared__ int s_any[T_STEPS];
    __shared__ int s_tlast;

    int tid = threadIdx.x;
    int cta = blockIdx.x;
    int rt = cta >> 4;
    int rbase = rt << 5;
    int ct = cta & 15;
    int c1base = ct << 5;
    int c3base = ct * 33;
    int b0 = cta << 1;

    for (int idx = tid; idx < 528 * 32; idx += NT) {
        int k = idx >> 5, cc = idx & 31;
        s_w1[idx] = W1[k * 512 + c1base + cc];
    }
    for (int idx = tid; idx < 512 * 32; idx += NT) {
        int k = idx >> 5, cc = idx & 31;
        s_w2[idx] = W2[k * 512 + c1base + cc];
    }
    for (int idx = tid; idx < 512 * 33; idx += NT) {
        int k = idx / 33, cc = idx - k * 33;
        s_w3[idx] = W3[k * 528 + c3base + cc];
    }
    for (int i = tid; i < 32; i += NT) {
        s_b1[i] = b1[c1base + i];
        s_b2[i] = b2[c1base + i];
        s_Bv[i] = Bv[i];
    }
    for (int i = tid; i < 33; i += NT) s_b3[i] = b3[c3base + i];
    for (int idx = tid; idx < 1024; idx += NT) {
        int k = idx >> 5, n = idx & 31;
        s_At[idx] = A[n * 32 + k];
    }
    for (int i = tid; i < T_STEPS; i += NT) s_any[i] = 0;
    __syncthreads();
    for (int idx = tid; idx < T_STEPS * B_SZ; idx += NT) {
        int t = idx % T_STEPS, b = idx / T_STEPS;
        if (mask[b * T_STEPS + t] > 0.f) s_any[t] = 1;
    }
    __syncthreads();
    if (tid == 0) {
        int tl = -1;
        for (int t = 0; t < T_STEPS; t++) if (s_any[t]) tl = t;
        s_tlast = tl;
    }
    __syncthreads();

    if (cta == 0)
        for (int i = tid; i < T_STEPS; i += NT) out[OFF_TIMES + i] = times[i];
    if (s_tlast < 0) {
        for (int j = tid; j < D0; j += NT) {
            out[OFF_LASTH + (size_t)b0 * D0 + j] = 0.f;
            out[OFF_LASTH + (size_t)(b0 + 1) * D0 + j] = 0.f;
        }
    }

    unsigned epoch = 0;

    for (int t = 0; t < T_STEPS; t++) {
        for (int s = 0; s < NSTEPS; s++) {
            // phase 1: layer1 (cn1 -> a1) + cn0 linear update
            gemm_tile(g_h + D0, HTOT, DIN, s_w1, s_b1, 32, rbase, c1base,
                      s_x, g_a1, 0, tid);
            __syncthreads();
            for (int it = tid; it < 1024; it += NT) {
                int p = it >> 5, k = it & 31;
                int b = b0 + (p >> 4), i = p & 15;
                s_x[k * 36 + p] = __ldcg(&g_h[b * HTOT + (i << 5) + k]);
            }
            if (tid < 32) {
                int b = b0 + (tid >> 4), i = tid & 15;
                s_hd[tid] = __ldcg(&g_h[b * HTOT + D0 + i]);
            }
            __syncthreads();
            if (tid < 256) {
                int n = tid & 31, pg = tid >> 5;
                float c0 = 0.f, c1v = 0.f, c2 = 0.f, c3 = 0.f;
                const float* ap = s_At + n;
                const float* xp = s_x + (pg << 2);
                #pragma unroll
                for (int k = 0; k < 32; k++) {
                    float w = ap[k << 5];
                    float4 xv = *(const float4*)(xp + k * 36);
                    c0  = fmaf(xv.x, w, c0);
                    c1v = fmaf(xv.y, w, c1v);
                    c2  = fmaf(xv.z, w, c2);
                    c3  = fmaf(xv.w, w, c3);
                }
                float bvn = s_Bv[n];
                float cs[4] = { c0, c1v, c2, c3 };
                #pragma unroll
                for (int j = 0; j < 4; j++) {
                    int p = (pg << 2) + j;
                    int b = b0 + (p >> 4), i = p & 15;
                    float oldv = s_x[n * 36 + p];
                    g_h[b * HTOT + (i << 5) + n] =
                        oldv + DTc * (cs[j] + bvn * s_hd[p]);
                }
            }
            grid_bar(epoch);

            // phase 2: layer2 (a1 -> a2)
            gemm_tile(g_a1, HID, HID, s_w2, s_b2, 32, rbase, c1base,
                      s_x, g_a2, 0, tid);
            grid_bar(epoch);

            // phase 3: layer3 (a2 -> cn1 += DT*driver)
            gemm_tile(g_a2, HID, HID, s_w3, s_b3, 33, rbase, c3base,
                      s_x, 0, 1, tid);
            grid_bar(epoch);
        }

        // observation update for this CTA's 2 batch rows
        for (int rb = 0; rb < 2; rb++) {
            int b = b0 + rb;
            float m = mask[b * T_STEPS + t];
            for (int i = tid; i < IDIM; i += NT) {
                float p = __ldcg(&g_h[b * HTOT + D0 + i]);
                int oi = (b * T_STEPS + t) * IDIM + i;
                out[OFF_PRED + oi] = p;
                out[OFF_TRAJ + oi] = p;
                if (m > 0.f)
                    g_h[b * HTOT + D0 + i] = Y[(b * T_STEPS + t) * IDIM + i];
            }
            if (m > 0.f) {
                for (int j = tid; j < D0; j += NT) {
                    float c = __ldcg(&g_h[b * HTOT + j]);
                    g_h[b * HTOT + D0 + IDIM + j] = c;
                }
            }
        }
        __threadfence();
        __syncthreads();
        if (t == s_tlast) {
            for (int rb = 0; rb < 2; rb++) {
                int b = b0 + rb;
                for (int j = tid; j < D0; j += NT)
                    out[OFF_LASTH + (size_t)b * D0 + j] =
                        __ldcg(&g_h[b * HTOT + j]);
            }
        }
        if (t == T_STEPS - 1) {
            for (int rb = 0; rb < 2; rb++) {
                int b = b0 + rb;
                for (int j = tid; j < HTOT; j += NT)
                    out[OFF_HFIN + (size_t)b * HTOT + j] =
                        __ldcg(&g_h[b * HTOT + j]);
            }
        }
        grid_bar(epoch);
    }
}

extern "C" void kernel_launch(void* const* d_in, const int* in_sizes, int n_in,
                              void* d_out, int out_size) {
    const float* times = (const float*)d_in[0];
    const float* Y     = (const float*)d_in[1];
    const float* mask  = (const float*)d_in[2];
    const float* A     = (const float*)d_in[3];
    const float* Bv    = (const float*)d_in[4];
    const float* W1    = (const float*)d_in[5];
    const float* b1    = (const float*)d_in[6];
    const float* W2    = (const float*)d_in[7];
    const float* b2    = (const float*)d_in[8];
    const float* W3    = (const float*)d_in[9];
    const float* b3    = (const float*)d_in[10];
    float* out = (float*)d_out;

    cudaFuncSetAttribute(cnode_kernel,
                         cudaFuncAttributeMaxDynamicSharedMemorySize,
                         SMEM_BYTES);
    init_kernel<<<NCTA, 256>>>();
    cnode_kernel<<<NCTA, NT, SMEM_BYTES>>>(times, Y, mask, A, Bv,
                                           W1, b1, W2, b2, W3, b3, out);
}

// round 9
// speedup vs baseline: 1.4577x; 1.4577x over previous
#include <cuda_runtime.h>

#define B_SZ    256
#define T_STEPS 50
#define IDIM    16
#define D0      512
#define DIN     528
#define HID     512
#define HTOT    1040
#define DTc     0.05f
#define NSTEPS  5
#define NCTA    128
#define NT      288

#define OFF_PRED  0
#define OFF_TRAJ  204800
#define OFF_TIMES 409600
#define OFF_LASTH 409650
#define OFF_HFIN  540722

// smem layout (floats)
#define SM_W1   0
#define SM_W2   16896
#define SM_W3   33280
#define SM_A    50176
#define SM_XP   51200
#define SM_B1   55424
#define SM_B2   55456
#define SM_B3   55488
#define SM_BV   55524
#define SM_HD   55556
#define SMEM_FLOATS 55588
#define SMEM_BYTES  (SMEM_FLOATS * 4)

typedef unsigned long long u64;

__device__ __align__(16) float g_hT[HTOT * B_SZ];   // col-major [c][b]
__device__ __align__(16) float g_a1T[HID * B_SZ];
__device__ __align__(16) float g_a2T[HID * B_SZ];
__device__ unsigned g_arr[8];
__device__ volatile unsigned g_rel[8];

__global__ void init_kernel() {
    int idx = blockIdx.x * blockDim.x + threadIdx.x;
    if (idx < 8) { g_arr[idx] = 0; *(unsigned*)&g_rel[idx] = 0; }
    int stride = gridDim.x * blockDim.x;
    for (int i = idx; i < HTOT * B_SZ; i += stride) g_hT[i] = 0.f;
}

__device__ __forceinline__ void group_bar(int gid, unsigned &epoch) {
    __syncthreads();
    if (threadIdx.x == 0) {
        __threadfence();
        epoch++;
        unsigned prev = atomicAdd(&g_arr[gid], 1u);
        if (prev + 1u == epoch * 16u) {
            g_rel[gid] = epoch;
            __threadfence();
        } else {
            while (g_rel[gid] < epoch) { }
            __threadfence();
        }
    }
    __syncthreads();
}

__device__ __forceinline__ unsigned smem_u32(const void* p) {
    unsigned r;
    asm("{ .reg .u64 t; cvta.to.shared.u64 t, %1; cvt.u32.u64 %0, t; }"
        : "=r"(r) : "l"(p));
    return r;
}
__device__ __forceinline__ void cp16(unsigned dst, const float* src) {
    asm volatile("cp.async.cg.shared.global [%0], [%1], 16;"
                 :: "r"(dst), "l"(__cvta_generic_to_global(src)));
}
#define CP_COMMIT() asm volatile("cp.async.commit_group;")
#define CP_WAIT0()  asm volatile("cp.async.wait_group 0;")

__device__ __forceinline__ void fma2(u64 &d, u64 a, u64 b) {
    asm("fma.rn.f32x2 %0, %1, %2, %0;" : "+l"(d) : "l"(a), "l"(b));
}
__device__ __forceinline__ void lds_x(u64 &a, u64 &b, unsigned addr) {
    asm volatile("ld.shared.v2.u64 {%0, %1}, [%2];"
                 : "=l"(a), "=l"(b) : "r"(addr));
}
__device__ __forceinline__ float lds_f(unsigned addr) {
    float r;
    asm volatile("ld.shared.f32 %0, [%1];" : "=f"(r) : "r"(addr));
    return r;
}
__device__ __forceinline__ u64 dup2(float w) {
    u64 r; asm("mov.b64 %0, {%1, %1};" : "=l"(r) : "f"(w)); return r;
}
__device__ __forceinline__ void unpk(u64 v, float &lo, float &hi) {
    asm("mov.b64 {%0, %1}, %2;" : "=f"(lo), "=f"(hi) : "l"(v));
}

// OUT(32 rows x NCOLS cols) = act(X^T slab). X col-major [K][256].
// MODE 0: dstT[(cbase+cc)*256+row] = relu(v + b)
// MODE 1: g_hT[(512+cbase+cc)*256+row] += DT*(v + b)
template<int K, int NCOLS, int MODE>
__device__ void layer_gemm(const float* __restrict__ XT,
                           unsigned sW_u32, const float* __restrict__ sb,
                           float* __restrict__ dstT,
                           int rbase, int cbase,
                           float* __restrict__ xp, unsigned xp_u32, int tid)
{
    constexpr int CH = K / 8;
    for (int i = tid; i < CH * 8; i += NT) {
        int k = i >> 3, seg = i & 7;
        cp16(xp_u32 + (unsigned)((k * 32 + seg * 4) * 4),
             XT + k * 256 + rbase + seg * 4);
    }
    CP_COMMIT();

    int cc = tid & 31;
    int rg = tid >> 5;               // 0..8
    u64 acc01 = 0ull, acc23 = 0ull;
    float accs = 0.f;                // warp 8 (col 32) scalar, NCOLS==33 only
    unsigned w_it  = sW_u32 + (unsigned)(cc * 4);
    unsigned w8_it = sW_u32 + 32u * 4u;

    for (int c = 0; c < 8; c++) {
        CP_WAIT0();
        __syncthreads();
        if (c + 1 < 8) {
            const float* Xc = XT + (c + 1) * CH * 256;
            unsigned xb = xp_u32 + (unsigned)(((c + 1) & 1) * CH * 32 * 4);
            for (int i = tid; i < CH * 8; i += NT) {
                int k = i >> 3, seg = i & 7;
                cp16(xb + (unsigned)((k * 32 + seg * 4) * 4),
                     Xc + k * 256 + rbase + seg * 4);
            }
        }
        CP_COMMIT();
        unsigned xs = xp_u32 + (unsigned)((c & 1) * CH * 32 * 4);
        if (rg < 8) {
            unsigned xa = xs + (unsigned)(rg * 16);
            #pragma unroll 4
            for (int k = 0; k < CH; k++) {
                float w = lds_f(w_it); w_it += NCOLS * 4;
                u64 x01, x23;
                lds_x(x01, x23, xa); xa += 128;
                u64 wd = dup2(w);
                fma2(acc01, x01, wd);
                fma2(acc23, x23, wd);
            }
        } else if (NCOLS == 33) {
            unsigned xpf = xs + (unsigned)((tid & 31) * 4);
            #pragma unroll 4
            for (int k = 0; k < CH; k++) {
                float x = lds_f(xpf); xpf += 128;
                float w = lds_f(w8_it); w8_it += 33 * 4;
                accs = fmaf(x, w, accs);
            }
        }
    }

    if (rg < 8) {
        float b = sb[cc];
        float v0, v1, v2, v3;
        unpk(acc01, v0, v1); unpk(acc23, v2, v3);
        if (MODE == 0) {
            v0 = fmaxf(v0 + b, 0.f); v1 = fmaxf(v1 + b, 0.f);
            v2 = fmaxf(v2 + b, 0.f); v3 = fmaxf(v3 + b, 0.f);
            float2* p = (float2*)(dstT + (cbase + cc) * 256 + rbase + rg * 4);
            __stcg(p,     make_float2(v0, v1));
            __stcg(p + 1, make_float2(v2, v3));
        } else {
            float* hp = g_hT + (512 + cbase + cc) * 256 + rbase + rg * 4;
            float2 o0 = __ldcg((float2*)hp);
            float2 o1 = __ldcg((float2*)hp + 1);
            __stcg((float2*)hp,
                   make_float2(o0.x + DTc * (v0 + b), o0.y + DTc * (v1 + b)));
            __stcg((float2*)hp + 1,
                   make_float2(o1.x + DTc * (v2 + b), o1.y + DTc * (v3 + b)));
        }
    } else if (NCOLS == 33) {
        float b = sb[32];
        float* hp = g_hT + (512 + cbase + 32) * 256 + rbase + (tid & 31);
        __stcg(hp, __ldcg(hp) + DTc * (accs + b));
    }
}

__global__ void __launch_bounds__(NT, 1) cnode_kernel(
    const float* __restrict__ times, const float* __restrict__ Y,
    const float* __restrict__ mask,  const float* __restrict__ A,
    const float* __restrict__ Bv,
    const float* __restrict__ W1, const float* __restrict__ b1,
    const float* __restrict__ W2, const float* __restrict__ b2,
    const float* __restrict__ W3, const float* __restrict__ b3,
    float* __restrict__ out)
{
    extern __shared__ float sm[];
    float* sW1 = sm + SM_W1;
    float* sW2 = sm + SM_W2;
    float* sW3 = sm + SM_W3;
    float* sA  = sm + SM_A;
    float* xp  = sm + SM_XP;
    float* sb1 = sm + SM_B1;
    float* sb2 = sm + SM_B2;
    float* sb3 = sm + SM_B3;
    float* sBv = sm + SM_BV;
    float* sHd = sm + SM_HD;
    __shared__ int s_any[T_STEPS];
    __shared__ int s_tlast;

    unsigned xp_u32 = smem_u32(xp);
    unsigned sW1_u32 = smem_u32(sW1);
    unsigned sW2_u32 = smem_u32(sW2);
    unsigned sW3_u32 = smem_u32(sW3);
    unsigned sA_u32  = smem_u32(sA);
    int tid = threadIdx.x;
    int cta = blockIdx.x;
    int rt = cta >> 4;            // group id
    int rbase = rt << 5;          // 32 batch rows
    int ct = cta & 15;
    int c1base = ct << 5;
    int c3base = ct * 33;
    int b0 = cta << 1;

    // resident weight slabs (k-major)
    for (int idx = tid; idx < 528 * 32; idx += NT) {
        int k = idx >> 5, cc = idx & 31;
        sW1[idx] = W1[k * 512 + c1base + cc];
    }
    for (int idx = tid; idx < 512 * 32; idx += NT) {
        int k = idx >> 5, cc = idx & 31;
        sW2[idx] = W2[k * 512 + c1base + cc];
    }
    for (int idx = tid; idx < 512 * 33; idx += NT) {
        int k = idx / 33, cc = idx - k * 33;
        sW3[idx] = W3[k * 528 + c3base + cc];
    }
    for (int idx = tid; idx < 1024; idx += NT) {
        int k = idx >> 5, n = idx & 31;
        sA[idx] = A[n * 32 + k];
    }
    for (int i = tid; i < 32; i += NT) {
        sb1[i] = b1[c1base + i];
        sb2[i] = b2[c1base + i];
        sBv[i] = Bv[i];
    }
    for (int i = tid; i < 33; i += NT) sb3[i] = b3[c3base + i];
    for (int i = tid; i < T_STEPS; i += NT) s_any[i] = 0;
    __syncthreads();
    for (int idx = tid; idx < T_STEPS * B_SZ; idx += NT) {
        int t = idx % T_STEPS, b = idx / T_STEPS;
        if (mask[b * T_STEPS + t] > 0.f) s_any[t] = 1;
    }
    __syncthreads();
    if (tid == 0) {
        int tl = -1;
        for (int t = 0; t < T_STEPS; t++) if (s_any[t]) tl = t;
        s_tlast = tl;
    }
    __syncthreads();

    if (cta == 0)
        for (int i = tid; i < T_STEPS; i += NT) out[OFF_TIMES + i] = times[i];
    if (s_tlast < 0) {
        for (int j = tid; j < D0; j += NT) {
            out[OFF_LASTH + (size_t)b0 * D0 + j] = 0.f;
            out[OFF_LASTH + (size_t)(b0 + 1) * D0 + j] = 0.f;
        }
    }

    int cc = tid & 31, rg = tid >> 5;
    unsigned epoch = 0;

    for (int t = 0; t < T_STEPS; t++) {
        for (int s = 0; s < NSTEPS; s++) {
            // ---- phase 1: layer1 (cn1 -> a1) + cn0 LMU update ----
            layer_gemm<528, 32, 0>(g_hT + 512 * 256, sW1_u32, sb1, g_a1T,
                                   rbase, c1base, xp, xp_u32, tid);
            __syncthreads();
            // stage cn0 block [32k x 32r] for i = ct
            for (int i = tid; i < 256; i += NT) {
                int k = i >> 3, seg = i & 7;
                cp16(xp_u32 + (unsigned)((k * 32 + seg * 4) * 4),
                     g_hT + (ct * 32 + k) * 256 + rbase + seg * 4);
            }
            CP_COMMIT();
            if (tid < 32)
                sHd[tid] = __ldcg(&g_hT[(512 + ct) * 256 + rbase + tid]);
            CP_WAIT0();
            __syncthreads();
            if (rg < 8) {
                u64 acc01 = 0ull, acc23 = 0ull;
                unsigned a_it = sA_u32 + (unsigned)(cc * 4);
                unsigned xa = xp_u32 + (unsigned)(rg * 16);
                #pragma unroll
                for (int k = 0; k < 32; k++) {
                    float w = lds_f(a_it); a_it += 128;
                    u64 x01, x23;
                    lds_x(x01, x23, xa); xa += 128;
                    u64 wd = dup2(w);
                    fma2(acc01, x01, wd);
                    fma2(acc23, x23, wd);
                }
                float c0, c1v, c2, c3;
                unpk(acc01, c0, c1v); unpk(acc23, c2, c3);
                float bv = sBv[cc];
                const float* oldp = xp + cc * 32 + rg * 4;
                float r0 = oldp[0] + DTc * (c0  + bv * sHd[rg * 4 + 0]);
                float r1 = oldp[1] + DTc * (c1v + bv * sHd[rg * 4 + 1]);
                float r2 = oldp[2] + DTc * (c2  + bv * sHd[rg * 4 + 2]);
                float r3 = oldp[3] + DTc * (c3  + bv * sHd[rg * 4 + 3]);
                float2* hp = (float2*)(g_hT + (ct * 32 + cc) * 256 + rbase + rg * 4);
                __stcg(hp,     make_float2(r0, r1));
                __stcg(hp + 1, make_float2(r2, r3));
            }
            group_bar(rt, epoch);

            // ---- phase 2: layer2 (a1 -> a2) ----
            layer_gemm<512, 32, 0>(g_a1T, sW2_u32, sb2, g_a2T,
                                   rbase, c1base, xp, xp_u32, tid);
            group_bar(rt, epoch);

            // ---- phase 3: layer3 (a2 -> cn1 += DT*driver) ----
            layer_gemm<512, 33, 1>(g_a2T, sW3_u32, sb3, 0,
                                   rbase, c3base, xp, xp_u32, tid);
            group_bar(rt, epoch);
        }

        // ---- observation for this CTA's 2 batch rows ----
        for (int rb = 0; rb < 2; rb++) {
            int b = b0 + rb;
            float m = mask[b * T_STEPS + t];
            if (tid < IDIM) {
                float p = __ldcg(&g_hT[(512 + tid) * 256 + b]);
                int oi = (b * T_STEPS + t) * IDIM + tid;
                out[OFF_PRED + oi] = p;
                out[OFF_TRAJ + oi] = p;
                if (m > 0.f)
                    g_hT[(512 + tid) * 256 + b] = Y[(b * T_STEPS + t) * IDIM + tid];
            }
            if (m > 0.f) {
                for (int j = tid; j < D0; j += NT) {
                    float c = __ldcg(&g_hT[j * 256 + b]);
                    __stcg(&g_hT[(528 + j) * 256 + b], c);
                }
            }
        }
        __threadfence();
        __syncthreads();
        if (t == s_tlast) {
            for (int rb = 0; rb < 2; rb++) {
                int b = b0 + rb;
                for (int j = tid; j < D0; j += NT)
                    out[OFF_LASTH + (size_t)b * D0 + j] =
                        __ldcg(&g_hT[j * 256 + b]);
            }
        }
        if (t == T_STEPS - 1) {
            for (int rb = 0; rb < 2; rb++) {
                int b = b0 + rb;
                for (int j = tid; j < HTOT; j += NT)
                    out[OFF_HFIN + (size_t)b * HTOT + j] =
                        __ldcg(&g_hT[j * 256 + b]);
            }
        }
        group_bar(rt, epoch);
    }
}

extern "C" void kernel_launch(void* const* d_in, const int* in_sizes, int n_in,
                              void* d_out, int out_size) {
    const float* times = (const float*)d_in[0];
    const float* Y     = (const float*)d_in[1];
    const float* mask  = (const float*)d_in[2];
    const float* A     = (const float*)d_in[3];
    const float* Bv    = (const float*)d_in[4];
    const float* W1    = (const float*)d_in[5];
    const float* b1    = (const float*)d_in[6];
    const float* W2    = (const float*)d_in[7];
    const float* b2    = (const float*)d_in[8];
    const float* W3    = (const float*)d_in[9];
    const float* b3    = (const float*)d_in[10];
    float* out = (float*)d_out;

    cudaFuncSetAttribute(cnode_kernel,
                         cudaFuncAttributeMaxDynamicSharedMemorySize,
                         SMEM_BYTES);
    init_kernel<<<NCTA, 256>>>();
    cnode_kernel<<<NCTA, NT, SMEM_BYTES>>>(times, Y, mask, A, Bv,
                                           W1, b1, W2, b2, W3, b3, out);
}

// round 11
// speedup vs baseline: 1.5220x; 1.0441x over previous
#include <cuda_runtime.h>

#define B_SZ    256
#define T_STEPS 50
#define IDIM    16
#define D0      512
#define DIN     528
#define HID     512
#define HTOT    1040
#define DTc     0.05f
#define NSTEPS  5
#define NCTA    128
#define NT      576
#define VT      288

#define OFF_PRED  0
#define OFF_TRAJ  204800
#define OFF_TIMES 409600
#define OFF_LASTH 409650
#define OFF_HFIN  540722

// smem layout (floats)
#define SM_W1   0
#define SM_W2   16896
#define SM_W3   33280
#define SM_A    50176
#define SM_XP   51200
#define SM_B1   55424
#define SM_B2   55456
#define SM_B3   55488
#define SM_BV   55524
#define SM_HD   55556
#define SMEM_FLOATS 55588
#define SMEM_BYTES  (SMEM_FLOATS * 4)

typedef unsigned long long u64;

__device__ __align__(16) float g_hT[HTOT * B_SZ];   // col-major [c][b]
__device__ __align__(16) float g_a1T[HID * B_SZ];
__device__ __align__(16) float g_a2T[HID * B_SZ];
__device__ unsigned g_arr[8];
__device__ volatile unsigned g_rel[8];

__global__ void init_kernel() {
    int idx = blockIdx.x * blockDim.x + threadIdx.x;
    if (idx < 8) { g_arr[idx] = 0; *(unsigned*)&g_rel[idx] = 0; }
    int stride = gridDim.x * blockDim.x;
    for (int i = idx; i < HTOT * B_SZ; i += stride) g_hT[i] = 0.f;
}

__device__ __forceinline__ void group_bar(int gid, unsigned &epoch) {
    __syncthreads();
    if (threadIdx.x == 0) {
        __threadfence();
        epoch++;
        unsigned prev = atomicAdd(&g_arr[gid], 1u);
        if (prev + 1u == epoch * 16u) {
            g_rel[gid] = epoch;
            __threadfence();
        } else {
            while (g_rel[gid] < epoch) { }
            __threadfence();
        }
    }
    __syncthreads();
}

__device__ __forceinline__ unsigned smem_u32(const void* p) {
    unsigned r;
    asm("{ .reg .u64 t; cvta.to.shared.u64 t, %1; cvt.u32.u64 %0, t; }"
        : "=r"(r) : "l"(p));
    return r;
}
__device__ __forceinline__ void cp16(unsigned dst, const float* src) {
    asm volatile("cp.async.cg.shared.global [%0], [%1], 16;"
                 :: "r"(dst), "l"(__cvta_generic_to_global(src)));
}
#define CP_COMMIT() asm volatile("cp.async.commit_group;")
#define CP_WAIT0()  asm volatile("cp.async.wait_group 0;")

__device__ __forceinline__ void fma2(u64 &d, u64 a, u64 b) {
    asm("fma.rn.f32x2 %0, %1, %2, %0;" : "+l"(d) : "l"(a), "l"(b));
}
__device__ __forceinline__ void add2(u64 &d, u64 a) {
    asm("add.rn.f32x2 %0, %0, %1;" : "+l"(d) : "l"(a));
}
__device__ __forceinline__ void lds_x(u64 &a, u64 &b, unsigned addr) {
    asm volatile("ld.shared.v2.u64 {%0, %1}, [%2];"
                 : "=l"(a), "=l"(b) : "r"(addr));
}
__device__ __forceinline__ float lds_f(unsigned addr) {
    float r;
    asm volatile("ld.shared.f32 %0, [%1];" : "=f"(r) : "r"(addr));
    return r;
}
__device__ __forceinline__ u64 dup2(float w) {
    u64 r; asm("mov.b64 %0, {%1, %1};" : "=l"(r) : "f"(w)); return r;
}
__device__ __forceinline__ void unpk(u64 v, float &lo, float &hi) {
    asm("mov.b64 {%0, %1}, %2;" : "=f"(lo), "=f"(hi) : "l"(v));
}

// OUT(32 rows x NCOLS cols) = act(X^T slab). X col-major [K][256].
// Split-K across two 9-warp halves; cross-half reduce via xp buffer 0.
// MODE 0: dstT[(cbase+cc)*256+row] = relu(v + b)
// MODE 1: g_hT[(512+cbase+cc)*256+row] += DT*(v + b)
template<int K, int NCOLS, int MODE>
__device__ void layer_gemm(const float* __restrict__ XT,
                           unsigned sW_u32, const float* __restrict__ sb,
                           float* __restrict__ dstT,
                           int rbase, int cbase,
                           float* __restrict__ xp, unsigned xp_u32, int tid)
{
    constexpr int CH  = K / 8;       // chunk k-size
    constexpr int CHH = CH / 2;      // per-half k-size
    for (int i = tid; i < CH * 8; i += NT) {
        int k = i >> 3, seg = i & 7;
        cp16(xp_u32 + (unsigned)((k * 32 + seg * 4) * 4),
             XT + k * 256 + rbase + seg * 4);
    }
    CP_COMMIT();

    int half = tid >= VT;
    int vtid = half ? tid - VT : tid;
    int cc = vtid & 31;
    int rg = vtid >> 5;              // 0..8
    u64 acc01 = 0ull, acc23 = 0ull;
    float accs = 0.f;                // col-32 scalar (NCOLS==33)

    for (int c = 0; c < 8; c++) {
        CP_WAIT0();
        __syncthreads();
        if (c + 1 < 8) {
            const float* Xc = XT + (c + 1) * CH * 256;
            unsigned xb = xp_u32 + (unsigned)(((c + 1) & 1) * CH * 32 * 4);
            for (int i = tid; i < CH * 8; i += NT) {
                int k = i >> 3, seg = i & 7;
                cp16(xb + (unsigned)((k * 32 + seg * 4) * 4),
                     Xc + k * 256 + rbase + seg * 4);
            }
        }
        CP_COMMIT();
        unsigned xs = xp_u32 + (unsigned)((c & 1) * CH * 32 * 4);
        int kbase = c * CH + half * CHH;
        if (rg < 8) {
            unsigned w_it = sW_u32 + (unsigned)((kbase * NCOLS + cc) * 4);
            unsigned xa = xs + (unsigned)(half * CHH * 128 + rg * 16);
            #pragma unroll 4
            for (int k = 0; k < CHH; k++) {
                float w = lds_f(w_it); w_it += NCOLS * 4;
                u64 x01, x23;
                lds_x(x01, x23, xa); xa += 128;
                u64 wd = dup2(w);
                fma2(acc01, x01, wd);
                fma2(acc23, x23, wd);
            }
        } else if (NCOLS == 33) {
            unsigned w8 = sW_u32 + (unsigned)((kbase * 33 + 32) * 4);
            unsigned xpf = xs + (unsigned)(half * CHH * 128 + cc * 4);
            #pragma unroll 4
            for (int k = 0; k < CHH; k++) {
                float x = lds_f(xpf); xpf += 128;
                float w = lds_f(w8); w8 += 33 * 4;
                accs = fmaf(x, w, accs);
            }
        }
    }

    // cross-half reduction: half 1 spills into xp buffer 0 (dead now)
    if (half) {
        if (rg < 8) {
            u64* red = (u64*)xp;
            red[(rg * 32 + cc) * 2 + 0] = acc01;
            red[(rg * 32 + cc) * 2 + 1] = acc23;
        } else if (NCOLS == 33) {
            xp[1024 + cc] = accs;
        }
    }
    __syncthreads();
    if (!half) {
        if (rg < 8) {
            const u64* red = (const u64*)xp;
            add2(acc01, red[(rg * 32 + cc) * 2 + 0]);
            add2(acc23, red[(rg * 32 + cc) * 2 + 1]);
            float b = sb[cc];
            float v0, v1, v2, v3;
            unpk(acc01, v0, v1); unpk(acc23, v2, v3);
            if (MODE == 0) {
                v0 = fmaxf(v0 + b, 0.f); v1 = fmaxf(v1 + b, 0.f);
                v2 = fmaxf(v2 + b, 0.f); v3 = fmaxf(v3 + b, 0.f);
                float2* p = (float2*)(dstT + (cbase + cc) * 256 + rbase + rg * 4);
                __stcg(p,     make_float2(v0, v1));
                __stcg(p + 1, make_float2(v2, v3));
            } else {
                float* hp = g_hT + (512 + cbase + cc) * 256 + rbase + rg * 4;
                float2 o0 = __ldcg((float2*)hp);
                float2 o1 = __ldcg((float2*)hp + 1);
                __stcg((float2*)hp,
                       make_float2(o0.x + DTc * (v0 + b), o0.y + DTc * (v1 + b)));
                __stcg((float2*)hp + 1,
                       make_float2(o1.x + DTc * (v2 + b), o1.y + DTc * (v3 + b)));
            }
        } else if (NCOLS == 33) {
            accs += xp[1024 + cc];
            float b = sb[32];
            float* hp = g_hT + (512 + cbase + 32) * 256 + rbase + cc;
            __stcg(hp, __ldcg(hp) + DTc * (accs + b));
        }
    }
}

__global__ void __launch_bounds__(NT, 1) cnode_kernel(
    const float* __restrict__ times, const float* __restrict__ Y,
    const float* __restrict__ mask,  const float* __restrict__ A,
    const float* __restrict__ Bv,
    const float* __restrict__ W1, const float* __restrict__ b1,
    const float* __restrict__ W2, const float* __restrict__ b2,
    const float* __restrict__ W3, const float* __restrict__ b3,
    float* __restrict__ out)
{
    extern __shared__ float sm[];
    float* sW1 = sm + SM_W1;
    float* sW2 = sm + SM_W2;
    float* sW3 = sm + SM_W3;
    float* sA  = sm + SM_A;
    float* xp  = sm + SM_XP;
    float* sb1 = sm + SM_B1;
    float* sb2 = sm + SM_B2;
    float* sb3 = sm + SM_B3;
    float* sBv = sm + SM_BV;
    float* sHd = sm + SM_HD;
    __shared__ int s_any[T_STEPS];
    __shared__ int s_tlast;

    unsigned xp_u32 = smem_u32(xp);
    unsigned sW1_u32 = smem_u32(sW1);
    unsigned sW2_u32 = smem_u32(sW2);
    unsigned sW3_u32 = smem_u32(sW3);
    unsigned sA_u32  = smem_u32(sA);
    int tid = threadIdx.x;
    int cta = blockIdx.x;
    int rt = cta >> 4;            // group id
    int rbase = rt << 5;          // 32 batch rows
    int ct = cta & 15;
    int c1base = ct << 5;
    int c3base = ct * 33;
    int b0 = cta << 1;

    // resident weight slabs (k-major)
    for (int idx = tid; idx < 528 * 32; idx += NT) {
        int k = idx >> 5, cc = idx & 31;
        sW1[idx] = W1[k * 512 + c1base + cc];
    }
    for (int idx = tid; idx < 512 * 32; idx += NT) {
        int k = idx >> 5, cc = idx & 31;
        sW2[idx] = W2[k * 512 + c1base + cc];
    }
    for (int idx = tid; idx < 512 * 33; idx += NT) {
        int k = idx / 33, cc = idx - k * 33;
        sW3[idx] = W3[k * 528 + c3base + cc];
    }
    for (int idx = tid; idx < 1024; idx += NT) {
        int k = idx >> 5, n = idx & 31;
        sA[idx] = A[n * 32 + k];
    }
    for (int i = tid; i < 32; i += NT) {
        sb1[i] = b1[c1base + i];
        sb2[i] = b2[c1base + i];
        sBv[i] = Bv[i];
    }
    for (int i = tid; i < 33; i += NT) sb3[i] = b3[c3base + i];
    for (int i = tid; i < T_STEPS; i += NT) s_any[i] = 0;
    __syncthreads();
    for (int idx = tid; idx < T_STEPS * B_SZ; idx += NT) {
        int t = idx % T_STEPS, b = idx / T_STEPS;
        if (mask[b * T_STEPS + t] > 0.f) s_any[t] = 1;
    }
    __syncthreads();
    if (tid == 0) {
        int tl = -1;
        for (int t = 0; t < T_STEPS; t++) if (s_any[t]) tl = t;
        s_tlast = tl;
    }
    __syncthreads();

    if (cta == 0)
        for (int i = tid; i < T_STEPS; i += NT) out[OFF_TIMES + i] = times[i];
    if (s_tlast < 0) {
        for (int j = tid; j < D0; j += NT) {
            out[OFF_LASTH + (size_t)b0 * D0 + j] = 0.f;
            out[OFF_LASTH + (size_t)(b0 + 1) * D0 + j] = 0.f;
        }
    }

    int half = tid >= VT;
    int vtid = half ? tid - VT : tid;
    int cc = vtid & 31, rg = vtid >> 5;
    unsigned epoch = 0;

    for (int t = 0; t < T_STEPS; t++) {
        for (int s = 0; s < NSTEPS; s++) {
            // ---- phase 1: layer1 (cn1 -> a1) + cn0 LMU update ----
            layer_gemm<528, 32, 0>(g_hT + 512 * 256, sW1_u32, sb1, g_a1T,
                                   rbase, c1base, xp, xp_u32, tid);
            __syncthreads();
            // stage cn0 block [32k x 32r] for i = ct
            for (int i = tid; i < 256; i += NT) {
                int k = i >> 3, seg = i & 7;
                cp16(xp_u32 + (unsigned)((k * 32 + seg * 4) * 4),
                     g_hT + (ct * 32 + k) * 256 + rbase + seg * 4);
            }
            CP_COMMIT();
            if (tid < 32)
                sHd[tid] = __ldcg(&g_hT[(512 + ct) * 256 + rbase + tid]);
            CP_WAIT0();
            __syncthreads();
            if (!half && rg < 8) {
                u64 acc01 = 0ull, acc23 = 0ull;
                unsigned a_it = sA_u32 + (unsigned)(cc * 4);
                unsigned xa = xp_u32 + (unsigned)(rg * 16);
                #pragma unroll
                for (int k = 0; k < 32; k++) {
                    float w = lds_f(a_it); a_it += 128;
                    u64 x01, x23;
                    lds_x(x01, x23, xa); xa += 128;
                    u64 wd = dup2(w);
                    fma2(acc01, x01, wd);
                    fma2(acc23, x23, wd);
                }
                float c0, c1v, c2, c3;
                unpk(acc01, c0, c1v); unpk(acc23, c2, c3);
                float bv = sBv[cc];
                const float* oldp = xp + cc * 32 + rg * 4;
                float r0 = oldp[0] + DTc * (c0  + bv * sHd[rg * 4 + 0]);
                float r1 = oldp[1] + DTc * (c1v + bv * sHd[rg * 4 + 1]);
                float r2 = oldp[2] + DTc * (c2  + bv * sHd[rg * 4 + 2]);
                float r3 = oldp[3] + DTc * (c3  + bv * sHd[rg * 4 + 3]);
                float2* hp = (float2*)(g_hT + (ct * 32 + cc) * 256 + rbase + rg * 4);
                __stcg(hp,     make_float2(r0, r1));
                __stcg(hp + 1, make_float2(r2, r3));
            }
            group_bar(rt, epoch);

            // ---- phase 2: layer2 (a1 -> a2) ----
            layer_gemm<512, 32, 0>(g_a1T, sW2_u32, sb2, g_a2T,
                                   rbase, c1base, xp, xp_u32, tid);
            group_bar(rt, epoch);

            // ---- phase 3: layer3 (a2 -> cn1 += DT*driver) ----
            layer_gemm<512, 33, 1>(g_a2T, sW3_u32, sb3, 0,
                                   rbase, c3base, xp, xp_u32, tid);
            group_bar(rt, epoch);
        }

        // ---- observation for this CTA's 2 batch rows ----
        for (int rb = 0; rb < 2; rb++) {
            int b = b0 + rb;
            float m = mask[b * T_STEPS + t];
            if (tid < IDIM) {
                float p = __ldcg(&g_hT[(512 + tid) * 256 + b]);
                int oi = (b * T_STEPS + t) * IDIM + tid;
                out[OFF_PRED + oi] = p;
                out[OFF_TRAJ + oi] = p;
                if (m > 0.f)
                    g_hT[(512 + tid) * 256 + b] = Y[(b * T_STEPS + t) * IDIM + tid];
            }
            if (m > 0.f) {
                for (int j = tid; j < D0; j += NT) {
                    float c = __ldcg(&g_hT[j * 256 + b]);
                    __stcg(&g_hT[(528 + j) * 256 + b], c);
                }
            }
        }
        __threadfence();
        __syncthreads();
        if (t == s_tlast) {
            for (int rb = 0; rb < 2; rb++) {
                int b = b0 + rb;
                for (int j = tid; j < D0; j += NT)
                    out[OFF_LASTH + (size_t)b * D0 + j] =
                        __ldcg(&g_hT[j * 256 + b]);
            }
        }
        if (t == T_STEPS - 1) {
            for (int rb = 0; rb < 2; rb++) {
                int b = b0 + rb;
                for (int j = tid; j < HTOT; j += NT)
                    out[OFF_HFIN + (size_t)b * HTOT + j] =
                        __ldcg(&g_hT[j * 256 + b]);
            }
        }
        group_bar(rt, epoch);
    }
}

extern "C" void kernel_launch(void* const* d_in, const int* in_sizes, int n_in,
                              void* d_out, int out_size) {
    const float* times = (const float*)d_in[0];
    const float* Y     = (const float*)d_in[1];
    const float* mask  = (const float*)d_in[2];
    const float* A     = (const float*)d_in[3];
    const float* Bv    = (const float*)d_in[4];
    const float* W1    = (const float*)d_in[5];
    const float* b1    = (const float*)d_in[6];
    const float* W2    = (const float*)d_in[7];
    const float* b2    = (const float*)d_in[8];
    const float* W3    = (const float*)d_in[9];
    const float* b3    = (const float*)d_in[10];
    float* out = (float*)d_out;

    cudaFuncSetAttribute(cnode_kernel,
                         cudaFuncAttributeMaxDynamicSharedMemorySize,
                         SMEM_BYTES);
    init_kernel<<<NCTA, 256>>>();
    cnode_kernel<<<NCTA, NT, SMEM_BYTES>>>(times, Y, mask, A, Bv,
                                           W1, b1, W2, b2, W3, b3, out);
}

// round 15
// speedup vs baseline: 1.5678x; 1.0301x over previous
#include <cuda_runtime.h>

#define B_SZ    256
#define T_STEPS 50
#define IDIM    16
#define D0      512
#define DIN     528
#define HID     512
#define HTOT    1040
#define DTc     0.05f
#define NSTEPS  5
#define NCTA    128
#define NT      320

#define OFF_PRED  0
#define OFF_TRAJ  204800
#define OFF_TIMES 409600
#define OFF_LASTH 409650
#define OFF_HFIN  540722

// smem layout (floats)
#define SM_W1   0
#define SM_W2   16896
#define SM_W3   33280
#define SM_A    50176
#define SM_XP   51200
#define SM_B1   57536
#define SM_B2   57568
#define SM_B3   57600
#define SM_BV   57636
#define SMEM_FLOATS 57668
#define SMEM_BYTES  (SMEM_FLOATS * 4)

typedef unsigned long long u64;

__device__ __align__(16) float g_hT[HTOT * B_SZ];   // col-major [c][b]
__device__ __align__(16) float g_a1T[HID * B_SZ];
__device__ __align__(16) float g_a2T[HID * B_SZ];
__device__ unsigned g_arr[8];
__device__ volatile unsigned g_rel[8];

__global__ void init_kernel() {
    int idx = blockIdx.x * blockDim.x + threadIdx.x;
    if (idx < 8) { g_arr[idx] = 0; *(unsigned*)&g_rel[idx] = 0; }
    int stride = gridDim.x * blockDim.x;
    for (int i = idx; i < HTOT * B_SZ; i += stride) g_hT[i] = 0.f;
}

__device__ __forceinline__ void group_bar(int gid, unsigned &epoch) {
    __syncthreads();
    if (threadIdx.x == 0) {
        __threadfence();
        epoch++;
        unsigned prev = atomicAdd(&g_arr[gid], 1u);
        if (prev + 1u == epoch * 16u) {
            g_rel[gid] = epoch;
            __threadfence();
        } else {
            while (g_rel[gid] < epoch) { }
            __threadfence();
        }
    }
    __syncthreads();
}

__device__ __forceinline__ unsigned smem_u32(const void* p) {
    unsigned r;
    asm("{ .reg .u64 t; cvta.to.shared.u64 t, %1; cvt.u32.u64 %0, t; }"
        : "=r"(r) : "l"(p));
    return r;
}
__device__ __forceinline__ void cp16(unsigned dst, const float* src) {
    asm volatile("cp.async.cg.shared.global [%0], [%1], 16;"
                 :: "r"(dst), "l"(__cvta_generic_to_global(src)));
}
#define CP_COMMIT() asm volatile("cp.async.commit_group;")
#define CP_WAIT0()  asm volatile("cp.async.wait_group 0;")
#define CP_WAIT1()  asm volatile("cp.async.wait_group 1;")

__device__ __forceinline__ void fma2(u64 &d, u64 a, u64 b) {
    asm("fma.rn.f32x2 %0, %1, %2, %0;" : "+l"(d) : "l"(a), "l"(b));
}
__device__ __forceinline__ void add2(u64 &d, u64 a) {
    asm("add.rn.f32x2 %0, %0, %1;" : "+l"(d) : "l"(a));
}
__device__ __forceinline__ void lds_x(u64 &a, u64 &b, unsigned addr) {
    asm volatile("ld.shared.v2.u64 {%0, %1}, [%2];"
                 : "=l"(a), "=l"(b) : "r"(addr));
}
__device__ __forceinline__ float lds_f(unsigned addr) {
    float r;
    asm volatile("ld.shared.f32 %0, [%1];" : "=f"(r) : "r"(addr));
    return r;
}
__device__ __forceinline__ u64 dup2(float w) {
    u64 r; asm("mov.b64 %0, {%1, %1};" : "=l"(r) : "f"(w)); return r;
}
__device__ __forceinline__ void unpk(u64 v, float &lo, float &hi) {
    asm("mov.b64 {%0, %1}, %2;" : "=f"(lo), "=f"(hi) : "l"(v));
}

// OUT(32 rows x NCOLS cols) = act(X^T slab). X col-major [K][256].
// Thread org: tid 0..255 compute (half=tid>>7, cc=tid&31, rg=(tid>>5)&3 -> 8 rows),
// tid 256..287 col-32 half0, tid 288..319 col-32 half1 (NCOLS==33 only).
// 8 chunks, 3 buffers, prefetch distance 2 (wait_group 1).
// MODE 0: dstT[(cbase+cc)*256+row] = relu(v + b)
// MODE 1: g_hT[(512+cbase+cc)*256+row] += DT*(v + b)
template<int K, int NCOLS, int MODE>
__device__ void layer_gemm(const float* __restrict__ XT,
                           unsigned sW_u32, const float* __restrict__ sb,
                           float* __restrict__ dstT,
                           int rbase, int cbase,
                           float* __restrict__ xp, unsigned xp_u32, int tid)
{
    constexpr int CH  = K / 8;       // chunk k-size (66 or 64)
    constexpr int CHH = CH / 2;      // per-half k-size (33 or 32)
    // prefetch chunks 0 and 1
    #pragma unroll
    for (int pc = 0; pc < 2; pc++) {
        const float* Xc = XT + pc * CH * 256;
        unsigned xb = xp_u32 + (unsigned)(pc * CH * 32 * 4);
        for (int i = tid; i < CH * 8; i += NT) {
            int k = i >> 3, seg = i & 7;
            cp16(xb + (unsigned)((k * 32 + seg * 4) * 4),
                 Xc + k * 256 + rbase + seg * 4);
        }
        CP_COMMIT();
    }

    bool comp = tid < 256;
    int half  = (tid >> 7) & 1;      // compute-half for tid<256
    int vt    = tid & 127;
    int cc    = vt & 31;
    int rg    = (vt >> 5) & 3;       // 8 rows: rg*8..rg*8+7
    int ahalf = tid >= 288;          // aux col-32 half
    int alane = tid & 31;

    u64 a0 = 0ull, a1 = 0ull, a2 = 0ull, a3 = 0ull;
    float accs = 0.f;

    for (int c = 0; c < 8; c++) {
        CP_WAIT1();
        __syncthreads();
        if (c < 6) {
            const float* Xc = XT + (c + 2) * CH * 256;
            unsigned xb = xp_u32 + (unsigned)(((c + 2) % 3) * CH * 32 * 4);
            for (int i = tid; i < CH * 8; i += NT) {
                int k = i >> 3, seg = i & 7;
                cp16(xb + (unsigned)((k * 32 + seg * 4) * 4),
                     Xc + k * 256 + rbase + seg * 4);
            }
        }
        CP_COMMIT();
        unsigned xs = xp_u32 + (unsigned)((c % 3) * CH * 32 * 4);
        if (comp) {
            unsigned w_it = sW_u32 +
                (unsigned)(((c * CH + half * CHH) * NCOLS + cc) * 4);
            unsigned xa = xs + (unsigned)(half * CHH * 128 + rg * 32);
            #pragma unroll 4
            for (int k = 0; k < CHH; k++) {
                float w = lds_f(w_it); w_it += NCOLS * 4;
                u64 x01, x23, x45, x67;
                lds_x(x01, x23, xa);
                lds_x(x45, x67, xa + 16);
                xa += 128;
                u64 wd = dup2(w);
                fma2(a0, x01, wd);
                fma2(a1, x23, wd);
                fma2(a2, x45, wd);
                fma2(a3, x67, wd);
            }
        } else if (NCOLS == 33) {
            unsigned w8 = sW_u32 +
                (unsigned)(((c * CH + ahalf * CHH) * 33 + 32) * 4);
            unsigned xpf = xs + (unsigned)(ahalf * CHH * 128 + alane * 4);
            #pragma unroll 4
            for (int k = 0; k < CHH; k++) {
                float x = lds_f(xpf); xpf += 128;
                float w = lds_f(w8); w8 += 33 * 4;
                accs = fmaf(x, w, accs);
            }
        }
    }

    // spill half1 into buffer 0 region (chunk 7 computes out of buffer 1)
    if (comp && half) {
        u64* red = (u64*)xp;
        red[vt * 4 + 0] = a0; red[vt * 4 + 1] = a1;
        red[vt * 4 + 2] = a2; red[vt * 4 + 3] = a3;
    } else if (!comp && ahalf && NCOLS == 33) {
        xp[1024 + alane] = accs;
    }
    __syncthreads();
    if (comp && !half) {
        const u64* red = (const u64*)xp;
        add2(a0, red[vt * 4 + 0]); add2(a1, red[vt * 4 + 1]);
        add2(a2, red[vt * 4 + 2]); add2(a3, red[vt * 4 + 3]);
        float b = sb[cc];
        float v0, v1, v2, v3, v4, v5, v6, v7;
        unpk(a0, v0, v1); unpk(a1, v2, v3);
        unpk(a2, v4, v5); unpk(a3, v6, v7);
        if (MODE == 0) {
            float4 o0 = make_float4(fmaxf(v0 + b, 0.f), fmaxf(v1 + b, 0.f),
                                    fmaxf(v2 + b, 0.f), fmaxf(v3 + b, 0.f));
            float4 o1 = make_float4(fmaxf(v4 + b, 0.f), fmaxf(v5 + b, 0.f),
                                    fmaxf(v6 + b, 0.f), fmaxf(v7 + b, 0.f));
            float4* p = (float4*)(dstT + (cbase + cc) * 256 + rbase + rg * 8);
            __stcg(p,     o0);
            __stcg(p + 1, o1);
        } else {
            float* hp = g_hT + (512 + cbase + cc) * 256 + rbase + rg * 8;
            float4 o0 = __ldcg((float4*)hp);
            float4 o1 = __ldcg((float4*)hp + 1);
            o0.x += DTc * (v0 + b); o0.y += DTc * (v1 + b);
            o0.z += DTc * (v2 + b); o0.w += DTc * (v3 + b);
            o1.x += DTc * (v4 + b); o1.y += DTc * (v5 + b);
            o1.z += DTc * (v6 + b); o1.w += DTc * (v7 + b);
            __stcg((float4*)hp,     o0);
            __stcg((float4*)hp + 1, o1);
        }
    } else if (!comp && !ahalf && NCOLS == 33) {
        accs += xp[1024 + alane];
        float b = sb[32];
        float* hp = g_hT + (512 + cbase + 32) * 256 + rbase + alane;
        __stcg(hp, __ldcg(hp) + DTc * (accs + b));
    }
}

__global__ void __launch_bounds__(NT, 1) cnode_kernel(
    const float* __restrict__ times, const float* __restrict__ Y,
    const float* __restrict__ mask,  const float* __restrict__ A,
    const float* __restrict__ Bv,
    const float* __restrict__ W1, const float* __restrict__ b1,
    const float* __restrict__ W2, const float* __restrict__ b2,
    const float* __restrict__ W3, const float* __restrict__ b3,
    float* __restrict__ out)
{
    extern __shared__ float sm[];
    float* sW1 = sm + SM_W1;
    float* sW2 = sm + SM_W2;
    float* sW3 = sm + SM_W3;
    float* sA  = sm + SM_A;
    float* xp  = sm + SM_XP;
    float* sb1 = sm + SM_B1;
    float* sb2 = sm + SM_B2;
    float* sb3 = sm + SM_B3;
    float* sBv = sm + SM_BV;
    __shared__ float sHd[32];
    __shared__ int s_any[T_STEPS];
    __shared__ int s_tlast;

    unsigned xp_u32 = smem_u32(xp);
    unsigned sW1_u32 = smem_u32(sW1);
    unsigned sW2_u32 = smem_u32(sW2);
    unsigned sW3_u32 = smem_u32(sW3);
    unsigned sA_u32  = smem_u32(sA);
    int tid = threadIdx.x;
    int cta = blockIdx.x;
    int rt = cta >> 4;            // group id
    int rbase = rt << 5;          // 32 batch rows
    int ct = cta & 15;
    int c1base = ct << 5;
    int c3base = ct * 33;
    int b0 = cta << 1;

    // resident weight slabs (k-major)
    for (int idx = tid; idx < 528 * 32; idx += NT) {
        int k = idx >> 5, cc = idx & 31;
        sW1[idx] = W1[k * 512 + c1base + cc];
    }
    for (int idx = tid; idx < 512 * 32; idx += NT) {
        int k = idx >> 5, cc = idx & 31;
        sW2[idx] = W2[k * 512 + c1base + cc];
    }
    for (int idx = tid; idx < 512 * 33; idx += NT) {
        int k = idx / 33, cc = idx - k * 33;
        sW3[idx] = W3[k * 528 + c3base + cc];
    }
    for (int idx = tid; idx < 1024; idx += NT) {
        int k = idx >> 5, n = idx & 31;
        sA[idx] = A[n * 32 + k];
    }
    for (int i = tid; i < 32; i += NT) {
        sb1[i] = b1[c1base + i];
        sb2[i] = b2[c1base + i];
        sBv[i] = Bv[i];
    }
    for (int i = tid; i < 33; i += NT) sb3[i] = b3[c3base + i];
    for (int i = tid; i < T_STEPS; i += NT) s_any[i] = 0;
    __syncthreads();
    for (int idx = tid; idx < T_STEPS * B_SZ; idx += NT) {
        int t = idx % T_STEPS, b = idx / T_STEPS;
        if (mask[b * T_STEPS + t] > 0.f) s_any[t] = 1;
    }
    __syncthreads();
    if (tid == 0) {
        int tl = -1;
        for (int t = 0; t < T_STEPS; t++) if (s_any[t]) tl = t;
        s_tlast = tl;
    }
    __syncthreads();

    if (cta == 0)
        for (int i = tid; i < T_STEPS; i += NT) out[OFF_TIMES + i] = times[i];
    if (s_tlast < 0) {
        for (int j = tid; j < D0; j += NT) {
            out[OFF_LASTH + (size_t)b0 * D0 + j] = 0.f;
            out[OFF_LASTH + (size_t)(b0 + 1) * D0 + j] = 0.f;
        }
    }

    int cc = tid & 31;
    int rg = (tid >> 5) & 3;
    unsigned epoch = 0;

    for (int t = 0; t < T_STEPS; t++) {
        for (int s = 0; s < NSTEPS; s++) {
            // ---- phase 1: layer1 (cn1 -> a1) + cn0 LMU update ----
            layer_gemm<528, 32, 0>(g_hT + 512 * 256, sW1_u32, sb1, g_a1T,
                                   rbase, c1base, xp, xp_u32, tid);
            __syncthreads();
            // stage cn0 block [32k x 32p] for i = ct
            for (int i = tid; i < 256; i += NT) {
                int k = i >> 3, seg = i & 7;
                cp16(xp_u32 + (unsigned)((k * 32 + seg * 4) * 4),
                     g_hT + (ct * 32 + k) * 256 + rbase + seg * 4);
            }
            CP_COMMIT();
            if (tid < 32)
                sHd[tid] = __ldcg(&g_hT[(512 + ct) * 256 + rbase + tid]);
            CP_WAIT0();
            __syncthreads();
            if (tid < 128) {
                u64 a0 = 0ull, a1v = 0ull, a2 = 0ull, a3 = 0ull;
                unsigned a_it = sA_u32 + (unsigned)(cc * 4);
                unsigned xa = xp_u32 + (unsigned)(rg * 32);
                #pragma unroll
                for (int k = 0; k < 32; k++) {
                    float w = lds_f(a_it); a_it += 128;
                    u64 x01, x23, x45, x67;
                    lds_x(x01, x23, xa);
                    lds_x(x45, x67, xa + 16);
                    xa += 128;
                    u64 wd = dup2(w);
                    fma2(a0, x01, wd);
                    fma2(a1v, x23, wd);
                    fma2(a2, x45, wd);
                    fma2(a3, x67, wd);
                }
                float v0, v1, v2, v3, v4, v5, v6, v7;
                unpk(a0, v0, v1); unpk(a1v, v2, v3);
                unpk(a2, v4, v5); unpk(a3, v6, v7);
                float bv = sBv[cc];
                const float* oldp = xp + cc * 32 + rg * 8;
                float r0 = oldp[0] + DTc * (v0 + bv * sHd[rg * 8 + 0]);
                float r1 = oldp[1] + DTc * (v1 + bv * sHd[rg * 8 + 1]);
                float r2 = oldp[2] + DTc * (v2 + bv * sHd[rg * 8 + 2]);
                float r3 = oldp[3] + DTc * (v3 + bv * sHd[rg * 8 + 3]);
                float r4 = oldp[4] + DTc * (v4 + bv * sHd[rg * 8 + 4]);
                float r5 = oldp[5] + DTc * (v5 + bv * sHd[rg * 8 + 5]);
                float r6 = oldp[6] + DTc * (v6 + bv * sHd[rg * 8 + 6]);
                float r7 = oldp[7] + DTc * (v7 + bv * sHd[rg * 8 + 7]);
                float4* hp = (float4*)(g_hT + (ct * 32 + cc) * 256 + rbase + rg * 8);
                __stcg(hp,     make_float4(r0, r1, r2, r3));
                __stcg(hp + 1, make_float4(r4, r5, r6, r7));
            }
            group_bar(rt, epoch);

            // ---- phase 2: layer2 (a1 -> a2) ----
            layer_gemm<512, 32, 0>(g_a1T, sW2_u32, sb2, g_a2T,
                                   rbase, c1base, xp, xp_u32, tid);
            group_bar(rt, epoch);

            // ---- phase 3: layer3 (a2 -> cn1 += DT*driver) ----
            layer_gemm<512, 33, 1>(g_a2T, sW3_u32, sb3, 0,
                                   rbase, c3base, xp, xp_u32, tid);
            group_bar(rt, epoch);
        }

        // ---- observation for this CTA's 2 batch rows ----
        for (int rb = 0; rb < 2; rb++) {
            int b = b0 + rb;
            float m = mask[b * T_STEPS + t];
            if (tid < IDIM) {
                float p = __ldcg(&g_hT[(512 + tid) * 256 + b]);
                int oi = (b * T_STEPS + t) * IDIM + tid;
                out[OFF_PRED + oi] = p;
                out[OFF_TRAJ + oi] = p;
                if (m > 0.f)
                    g_hT[(512 + tid) * 256 + b] = Y[(b * T_STEPS + t) * IDIM + tid];
            }
            if (m > 0.f) {
                for (int j = tid; j < D0; j += NT) {
                    float c = __ldcg(&g_hT[j * 256 + b]);
                    __stcg(&g_hT[(528 + j) * 256 + b], c);
                }
            }
        }
        __threadfence();
        __syncthreads();
        if (t == s_tlast) {
            for (int rb = 0; rb < 2; rb++) {
                int b = b0 + rb;
                for (int j = tid; j < D0; j += NT)
                    out[OFF_LASTH + (size_t)b * D0 + j] =
                        __ldcg(&g_hT[j * 256 + b]);
            }
        }
        if (t == T_STEPS - 1) {
            for (int rb = 0; rb < 2; rb++) {
                int b = b0 + rb;
                for (int j = tid; j < HTOT; j += NT)
                    out[OFF_HFIN + (size_t)b * HTOT + j] =
                        __ldcg(&g_hT[j * 256 + b]);
            }
        }
        group_bar(rt, epoch);
    }
}

extern "C" void kernel_launch(void* const* d_in, const int* in_sizes, int n_in,
                              void* d_out, int out_size) {
    const float* times = (const float*)d_in[0];
    const float* Y     = (const float*)d_in[1];
    const float* mask  = (const float*)d_in[2];
    const float* A     = (const float*)d_in[3];
    const float* Bv    = (const float*)d_in[4];
    const float* W1    = (const float*)d_in[5];
    const float* b1    = (const float*)d_in[6];
    const float* W2    = (const float*)d_in[7];
    const float* b2    = (const float*)d_in[8];
    const float* W3    = (const float*)d_in[9];
    const float* b3    = (const float*)d_in[10];
    float* out = (float*)d_out;

    cudaFuncSetAttribute(cnode_kernel,
                         cudaFuncAttributeMaxDynamicSharedMemorySize,
                         SMEM_BYTES);
    init_kernel<<<NCTA, 256>>>();
    cnode_kernel<<<NCTA, NT, SMEM_BYTES>>>(times, Y, mask, A, Bv,
                                           W1, b1, W2, b2, W3, b3, out);
}